// round 14
// baseline (speedup 1.0000x reference)
#include <cuda_runtime.h>
#include <cuda_fp16.h>
#include <math.h>
#include <stdint.h>

#define BB 8
#define NSEQ 4096
#define DD 1024

#define THREADS 128
#define BK 64
// block tile 128(M) x 128(N) x 64(K); 4 warps of 64x64 (2 wm x 2 wn)
#define A_BYTES 16384               // 128*64*2
#define B_BYTES 16384
#define STAGE_BYTES (A_BYTES + B_BYTES)   // 32768
#define SMEM_BYTES (3*STAGE_BYTES)        // 98304 >= slab 67584
#define PADL 132                    // fp32 epilogue slab row stride

// ---------------- scratch (all single fp16) ----------------
__device__ __half g_xh[BB*NSEQ*DD];
__device__ __half g_Wh[4*DD*DD];
__device__ float  g_Vr32[BB*NSEQ*DD];
__device__ __half g_Vh[BB*NSEQ*DD];
__device__ __half g_Kth[BB*DD*NSEQ];   // [b][d][n]
__device__ __half g_Qth[BB*DD*NSEQ];   // [b][e][n]
__device__ __half g_Ath[BB*DD*DD];     // [b][e][d]
__device__ float  g_sK[BB*DD], g_sQ[BB*DD];

// ---------------- asm helpers ----------------
__device__ __forceinline__ uint32_t smem_u32(const void* p){
    uint32_t a;
    asm("{ .reg .u64 t; cvta.to.shared.u64 t, %1; cvt.u32.u64 %0, t; }"
        : "=r"(a) : "l"(p));
    return a;
}
__device__ __forceinline__ void cp16(uint32_t s, const void* g){
    asm volatile("cp.async.cg.shared.global [%0], [%1], 16;"
                 :: "r"(s), "l"(__cvta_generic_to_global(g)) : "memory");
}
#define CP_COMMIT() asm volatile("cp.async.commit_group;" ::: "memory")
#define CP_WAIT1()  asm volatile("cp.async.wait_group 1;" ::: "memory")

__device__ __forceinline__ void ldsm4(uint32_t addr, uint32_t* r){
    asm volatile("ldmatrix.sync.aligned.m8n8.x4.shared.b16 {%0,%1,%2,%3}, [%4];"
        : "=r"(r[0]),"=r"(r[1]),"=r"(r[2]),"=r"(r[3]) : "r"(addr));
}
__device__ __forceinline__ void mma16816(float* d, const uint32_t* a, const uint32_t* b){
    asm volatile("mma.sync.aligned.m16n8k16.row.col.f32.f16.f16.f32 "
        "{%0,%1,%2,%3}, {%4,%5,%6,%7}, {%8,%9}, {%0,%1,%2,%3};"
        : "+f"(d[0]),"+f"(d[1]),"+f"(d[2]),"+f"(d[3])
        : "r"(a[0]),"r"(a[1]),"r"(a[2]),"r"(a[3]), "r"(b[0]),"r"(b[1]));
}

// SW128 swizzle: 128B rows (64 fp16), 16B chunk c in 0..7
__device__ __forceinline__ uint32_t swz(int r, int c){
    return (uint32_t)(r*128 + ((c ^ (r&7))<<4));
}

// ---------------- pipeline pieces ----------------
__device__ __forceinline__ void load_stage(uint32_t sb,
        const __half* Ah, int lda, const __half* Bh, int ldb, int k0, int tid)
{
    #pragma unroll
    for (int l = 0; l < 8; ++l){              // A: 128 rows x 8 chunks
        int idx = tid + l*THREADS;
        int r = idx >> 3, c = idx & 7;
        cp16(sb + swz(r, c), Ah + (size_t)r*lda + k0 + c*8);
    }
    #pragma unroll
    for (int l = 0; l < 8; ++l){              // B: 128 rows x 8 chunks
        int idx = tid + l*THREADS;
        int r = idx >> 3, c = idx & 7;
        cp16(sb + A_BYTES + swz(r, c), Bh + (size_t)r*ldb + k0 + c*8);
    }
}

// 64x64 warp tile: per kc, 4 A-ldsm + 4 B-ldsm feed 32 MMAs (B in 2 halves
// to cap live registers). smem-read duplication: A x2, B x2 (vs x2/x4 before).
__device__ __forceinline__ void compute_stage(uint32_t sb, int lane,
                                              int wm, int wn, float acc[4][8][4])
{
    const int rw = lane & 7, tt = lane >> 3;
    #pragma unroll
    for (int kc = 0; kc < 4; ++kc){
        uint32_t ah[4][4];
        #pragma unroll
        for (int mi = 0; mi < 4; ++mi){
            int row = wm*64 + mi*16 + rw + ((tt&1)<<3);
            int ch  = 2*kc + (tt>>1);
            ldsm4(sb + swz(row, ch), ah[mi]);
        }
        #pragma unroll
        for (int h = 0; h < 2; ++h){
            uint32_t bh[4][2];
            #pragma unroll
            for (int jp = 0; jp < 2; ++jp){
                int row = wn*64 + (h*2+jp)*16 + rw + ((tt>>1)<<3);
                int ch  = 2*kc + (tt&1);
                uint32_t t4[4];
                ldsm4(sb + A_BYTES + swz(row, ch), t4);
                bh[2*jp][0]=t4[0]; bh[2*jp][1]=t4[1];
                bh[2*jp+1][0]=t4[2]; bh[2*jp+1][1]=t4[3];
            }
            #pragma unroll
            for (int mi = 0; mi < 4; ++mi)
                #pragma unroll
                for (int nj = 0; nj < 4; ++nj)
                    mma16816(acc[mi][h*4+nj], ah[mi], bh[nj]);
        }
    }
}

// single __syncthreads per iteration
__device__ __forceinline__ void gemm_ml(const __half* Ah, int lda,
        const __half* Bh, int ldb, int niter, uint32_t su, float acc[4][8][4])
{
    const int tid = threadIdx.x;
    const int lane = tid & 31, w = tid >> 5, wm = w & 1, wn = w >> 1;
    load_stage(su,               Ah, lda, Bh, ldb, 0,  tid); CP_COMMIT();
    load_stage(su + STAGE_BYTES, Ah, lda, Bh, ldb, BK, tid); CP_COMMIT();
    for (int i = 0; i < niter; ++i){
        CP_WAIT1();
        __syncthreads();
        if (i + 2 < niter)
            load_stage(su + ((i+2)%3)*STAGE_BYTES, Ah, lda, Bh, ldb, (i+2)*BK, tid);
        CP_COMMIT();
        compute_stage(su + (i%3)*STAGE_BYTES, lane, wm, wn, acc);
    }
}

// ---------------- epilogue helpers ----------------
__device__ __forceinline__ void acc_to_sm(float* sm, int lane, int wm, int wn,
                                          float acc[4][8][4], bool transposed)
{
    #pragma unroll
    for (int mi = 0; mi < 4; ++mi)
        #pragma unroll
        for (int nj = 0; nj < 8; ++nj){
            int row = wm*64 + mi*16 + (lane>>2);
            int col = wn*64 + nj*8 + 2*(lane&3);
            if (!transposed){
                sm[row*PADL + col]     = acc[mi][nj][0];
                sm[row*PADL + col + 1] = acc[mi][nj][1];
                sm[(row+8)*PADL + col]     = acc[mi][nj][2];
                sm[(row+8)*PADL + col + 1] = acc[mi][nj][3];
            } else {
                sm[col*PADL + row]       = acc[mi][nj][0];
                sm[(col+1)*PADL + row]   = acc[mi][nj][1];
                sm[col*PADL + row + 8]   = acc[mi][nj][2];
                sm[(col+1)*PADL + row+8] = acc[mi][nj][3];
            }
        }
}

// ---------------- prep kernels ----------------
__global__ __launch_bounds__(256) void conv_x(const float* __restrict__ x){
    size_t i = ((size_t)blockIdx.x*256 + threadIdx.x)*4;
    float4 v = *(const float4*)(x + i);
    __half2* ph = (__half2*)(g_xh + i);
    ph[0] = __halves2half2(__float2half_rn(v.x), __float2half_rn(v.y));
    ph[1] = __halves2half2(__float2half_rn(v.z), __float2half_rn(v.w));
}
__global__ __launch_bounds__(256) void conv_w(const float* __restrict__ Wvr,
    const float* __restrict__ Wvi, const float* __restrict__ Wk, const float* __restrict__ Wq){
    size_t i = ((size_t)blockIdx.x*256 + threadIdx.x)*4;
    int w = (int)(i >> 20);
    size_t off = i & ((1u<<20)-1);
    const float* W = (w==0)?Wvr:(w==1)?Wvi:(w==2)?Wk:Wq;
    float4 v = *(const float4*)(W + off);
    __half2* ph = (__half2*)(g_Wh + i);
    ph[0] = __halves2half2(__float2half_rn(v.x), __float2half_rn(v.y));
    ph[1] = __halves2half2(__float2half_rn(v.z), __float2half_rn(v.w));
}

// ---------------- projections: Vr, K, Q ----------------
// grid (24, 256): w = x>>3 in {0:Vr, 1:K, 2:Q}, col block = (x&7)*128
__global__ __launch_bounds__(THREADS, 2) void proj_mma(const float* __restrict__ bvr,
    const float* __restrict__ bk, const float* __restrict__ bq)
{
    extern __shared__ char smem[];
    uint32_t su = smem_u32(smem);
    const int tid = threadIdx.x;
    const int lane = tid & 31, wrp = tid >> 5, wm = wrp & 1, wn = wrp >> 1;
    const int w  = blockIdx.x >> 3;
    const int gn = (blockIdx.x & 7) * 128;
    const int m0 = blockIdx.y * 128;
    const int wsel = (w==0) ? 0 : (w==1) ? 2 : 3;   // weight index in g_Wh

    const __half* Ah = g_xh + (size_t)m0*DD;
    const __half* Bh = g_Wh + (size_t)wsel*DD*DD + (size_t)gn*DD;
    const float* bias = (w==0)?bvr:(w==1)?bk:bq;

    float acc[4][8][4] = {};
    gemm_ml(Ah, DD, Bh, DD, DD/BK, su, acc);
    __syncthreads();

    float* sm = (float*)smem;
    if (w == 0){
        acc_to_sm(sm, lane, wm, wn, acc, false);
        __syncthreads();
        #pragma unroll
        for (int l = 0; l < 32; ++l){
            int idx = tid + l*THREADS;
            int row = idx >> 5, q = idx & 31;
            float4 v = *(float4*)&sm[row*PADL + q*4];
            float4 bv = *(const float4*)(bias + gn + q*4);
            v.x += bv.x; v.y += bv.y; v.z += bv.z; v.w += bv.w;
            *(float4*)(g_Vr32 + (size_t)(m0+row)*DD + gn + q*4) = v;
        }
    } else {
        acc_to_sm(sm, lane, wm, wn, acc, true);   // sm[d][n]
        __syncthreads();
        __half* dst = (w==1) ? g_Kth : g_Qth;
        const int b = m0 >> 12, n0 = m0 & 4095;
        #pragma unroll
        for (int l = 0; l < 32; ++l){
            int idx = tid + l*THREADS;
            int d = idx >> 5, q = idx & 31;
            float bcol = bias[gn + d];
            float4 v = *(float4*)&sm[d*PADL + q*4];
            size_t go = ((size_t)b*DD + gn + d)*NSEQ + n0 + q*4;
            __half2* ph = (__half2*)(dst + go);
            ph[0] = __halves2half2(__float2half_rn(v.x + bcol), __float2half_rn(v.y + bcol));
            ph[1] = __halves2half2(__float2half_rn(v.z + bcol), __float2half_rn(v.w + bcol));
        }
    }
}

// ---------------- Vi projection + fused GLU gate ----------------
__device__ __forceinline__ float gatef(float v){
    float sp = (v > 20.f) ? v : log1pf(expf(v));
    return tanhf(sp);
}
// grid (8, 256). Reads g_Vr32 (bias included), writes gated value fp16.
__global__ __launch_bounds__(THREADS, 2) void proj_vi(const float* __restrict__ bvi)
{
    extern __shared__ char smem[];
    uint32_t su = smem_u32(smem);
    const int tid = threadIdx.x;
    const int lane = tid & 31, wrp = tid >> 5, wm = wrp & 1, wn = wrp >> 1;
    const int gn = blockIdx.x * 128;
    const int m0 = blockIdx.y * 128;

    const __half* Ah = g_xh + (size_t)m0*DD;
    const __half* Bh = g_Wh + (size_t)1*DD*DD + (size_t)gn*DD;

    float acc[4][8][4] = {};
    gemm_ml(Ah, DD, Bh, DD, DD/BK, su, acc);
    __syncthreads();

    float* sm = (float*)smem;
    acc_to_sm(sm, lane, wm, wn, acc, false);
    __syncthreads();
    #pragma unroll
    for (int l = 0; l < 32; ++l){
        int idx = tid + l*THREADS;
        int row = idx >> 5, q = idx & 31;
        float4 vi = *(float4*)&sm[row*PADL + q*4];
        float4 bv = *(const float4*)(bvi + gn + q*4);
        size_t go = (size_t)(m0+row)*DD + gn + q*4;
        float4 vr = *(const float4*)(g_Vr32 + go);
        vr.x *= gatef(vi.x + bv.x); vr.y *= gatef(vi.y + bv.y);
        vr.z *= gatef(vi.z + bv.z); vr.w *= gatef(vi.w + bv.w);
        __half2* ph = (__half2*)(g_Vh + go);
        ph[0] = __halves2half2(__float2half_rn(vr.x), __float2half_rn(vr.y));
        ph[1] = __halves2half2(__float2half_rn(vr.z), __float2half_rn(vr.w));
    }
}

// ---------------- norms ----------------
__global__ __launch_bounds__(256) void norm_kernel(){
    const __half* Ph = blockIdx.z ? g_Qth : g_Kth;
    float*        S  = blockIdx.z ? g_sQ  : g_sK;
    const int b = blockIdx.y;
    const int d = blockIdx.x*8 + (threadIdx.x >> 5);
    const int lane = threadIdx.x & 31;
    size_t base = ((size_t)b*DD + d)*NSEQ;
    const __half2* rh = (const __half2*)(Ph + base);
    float s = 0.f;
    for (int f = lane; f < NSEQ/2; f += 32){
        float2 h = __half22float2(rh[f]);
        s = fmaf(h.x, h.x, s); s = fmaf(h.y, h.y, s);
    }
    #pragma unroll
    for (int off = 16; off > 0; off >>= 1)
        s += __shfl_xor_sync(0xffffffffu, s, off);
    if (lane == 0) S[b*DD + d] = 1.f / (sqrtf(s) + 1e-5f);
}

// ---------------- feature attention ----------------
__device__ __forceinline__ float smuf(float v){
    return 0.5f * (1.25f*v + 0.75f*v*erff(750000.f*v));
}
__global__ __launch_bounds__(THREADS, 2) void attn_mma(){
    extern __shared__ char smem[];
    uint32_t su = smem_u32(smem);
    const int tid = threadIdx.x;
    const int lane = tid & 31, wrp = tid >> 5, wm = wrp & 1, wn = wrp >> 1;
    const int b  = blockIdx.z;
    const int e0 = blockIdx.y * 128;
    const int d0 = blockIdx.x * 128;

    size_t qa = ((size_t)b*DD + e0)*NSEQ;
    size_t ka = ((size_t)b*DD + d0)*NSEQ;
    float acc[4][8][4] = {};
    gemm_ml(g_Qth + qa, NSEQ, g_Kth + ka, NSEQ, NSEQ/BK, su, acc);
    __syncthreads();

    float* sm = (float*)smem;
    acc_to_sm(sm, lane, wm, wn, acc, false);   // sm[e][d]
    __syncthreads();
    const float* sQ = g_sQ + b*DD;
    const float* sK = g_sK + b*DD;
    #pragma unroll
    for (int l = 0; l < 32; ++l){
        int idx = tid + l*THREADS;
        int row = idx >> 5, q = idx & 31;
        float sq = sQ[e0 + row];
        float4 sk = *(const float4*)(sK + d0 + q*4);
        float4 v = *(float4*)&sm[row*PADL + q*4];
        v.x = smuf(v.x * sq * sk.x); v.y = smuf(v.y * sq * sk.y);
        v.z = smuf(v.z * sq * sk.z); v.w = smuf(v.w * sq * sk.w);
        size_t go = ((size_t)b*DD + e0 + row)*DD + d0 + q*4;
        __half2* ph = (__half2*)(g_Ath + go);
        ph[0] = __halves2half2(__float2half_rn(v.x), __float2half_rn(v.y));
        ph[1] = __halves2half2(__float2half_rn(v.z), __float2half_rn(v.w));
    }
}

// ---------------- output ----------------
__global__ __launch_bounds__(THREADS, 2) void out_mma(float* __restrict__ outp){
    extern __shared__ char smem[];
    uint32_t su = smem_u32(smem);
    const int tid = threadIdx.x;
    const int lane = tid & 31, wrp = tid >> 5, wm = wrp & 1, wn = wrp >> 1;
    const int m0 = blockIdx.y * 128;     // global token
    const int e0 = blockIdx.x * 128;
    const int b  = m0 >> 12;

    size_t va = (size_t)m0*DD;
    size_t aa = ((size_t)b*DD + e0)*DD;
    float acc[4][8][4] = {};
    gemm_ml(g_Vh + va, DD, g_Ath + aa, DD, DD/BK, su, acc);
    __syncthreads();

    float* sm = (float*)smem;
    acc_to_sm(sm, lane, wm, wn, acc, false);   // sm[n][e]
    __syncthreads();
    #pragma unroll
    for (int l = 0; l < 32; ++l){
        int idx = tid + l*THREADS;
        int row = idx >> 5, q = idx & 31;
        float4 v = *(float4*)&sm[row*PADL + q*4];
        *(float4*)(outp + (size_t)(m0+row)*DD + e0 + q*4) = v;
    }
}

// ---------------- launch ----------------
extern "C" void kernel_launch(void* const* d_in, const int* in_sizes, int n_in,
                              void* d_out, int out_size)
{
    const float* x   = (const float*)d_in[0];
    const float* Wvr = (const float*)d_in[1];
    const float* bvr = (const float*)d_in[2];
    const float* Wvi = (const float*)d_in[3];
    const float* bvi = (const float*)d_in[4];
    const float* Wk  = (const float*)d_in[5];
    const float* bk  = (const float*)d_in[6];
    const float* Wq  = (const float*)d_in[7];
    const float* bq  = (const float*)d_in[8];
    float* out = (float*)d_out;

    cudaFuncSetAttribute(proj_mma, cudaFuncAttributeMaxDynamicSharedMemorySize, SMEM_BYTES);
    cudaFuncSetAttribute(proj_vi,  cudaFuncAttributeMaxDynamicSharedMemorySize, SMEM_BYTES);
    cudaFuncSetAttribute(attn_mma, cudaFuncAttributeMaxDynamicSharedMemorySize, SMEM_BYTES);
    cudaFuncSetAttribute(out_mma,  cudaFuncAttributeMaxDynamicSharedMemorySize, SMEM_BYTES);

    conv_x<<<BB*NSEQ*DD/(256*4), 256>>>(x);
    conv_w<<<4*DD*DD/(256*4), 256>>>(Wvr, Wvi, Wk, Wq);
    proj_mma<<<dim3(24, 256), THREADS, SMEM_BYTES>>>(bvr, bk, bq);
    proj_vi<<<dim3(8, 256), THREADS, SMEM_BYTES>>>(bvi);
    norm_kernel<<<dim3(DD/8, BB, 2), 256>>>();
    attn_mma<<<dim3(8, 8, BB), THREADS, SMEM_BYTES>>>();
    out_mma<<<dim3(8, 256), THREADS, SMEM_BYTES>>>(out);
}

// round 15
// speedup vs baseline: 1.1145x; 1.1145x over previous
#include <cuda_runtime.h>
#include <cuda_fp16.h>
#include <math.h>
#include <stdint.h>

#define BB 8
#define NSEQ 4096
#define DD 1024

#define THREADS 256
#define BK 64
// K/Q/attn/out: block 128x128x64, warp tile 32x64 (4 wm x 2 wn)
#define A_BYTES 16384               // 128*64*2
#define B_BYTES 16384
#define STAGE_BYTES (A_BYTES + B_BYTES)   // 32768
#define SMEM_BYTES (3*STAGE_BYTES)        // 98304 >= slab 67584
#define PADL 132                    // fp32 epilogue slab row stride

// ---------------- scratch (all single fp16) ----------------
__device__ __half g_xh[BB*NSEQ*DD];
__device__ __half g_Wh[4*DD*DD];
__device__ __half g_Vh[BB*NSEQ*DD];
__device__ __half g_Kth[BB*DD*NSEQ];   // [b][d][n]
__device__ __half g_Qth[BB*DD*NSEQ];   // [b][e][n]
__device__ __half g_Ath[BB*DD*DD];     // [b][e][d]
__device__ float  g_sK[BB*DD], g_sQ[BB*DD];

// ---------------- asm helpers ----------------
__device__ __forceinline__ uint32_t smem_u32(const void* p){
    uint32_t a;
    asm("{ .reg .u64 t; cvta.to.shared.u64 t, %1; cvt.u32.u64 %0, t; }"
        : "=r"(a) : "l"(p));
    return a;
}
__device__ __forceinline__ void cp16(uint32_t s, const void* g){
    asm volatile("cp.async.cg.shared.global [%0], [%1], 16;"
                 :: "r"(s), "l"(__cvta_generic_to_global(g)) : "memory");
}
#define CP_COMMIT() asm volatile("cp.async.commit_group;" ::: "memory")
#define CP_WAIT1()  asm volatile("cp.async.wait_group 1;" ::: "memory")

__device__ __forceinline__ void ldsm4(uint32_t addr, uint32_t* r){
    asm volatile("ldmatrix.sync.aligned.m8n8.x4.shared.b16 {%0,%1,%2,%3}, [%4];"
        : "=r"(r[0]),"=r"(r[1]),"=r"(r[2]),"=r"(r[3]) : "r"(addr));
}
__device__ __forceinline__ void mma16816(float* d, const uint32_t* a, const uint32_t* b){
    asm volatile("mma.sync.aligned.m16n8k16.row.col.f32.f16.f16.f32 "
        "{%0,%1,%2,%3}, {%4,%5,%6,%7}, {%8,%9}, {%0,%1,%2,%3};"
        : "+f"(d[0]),"+f"(d[1]),"+f"(d[2]),"+f"(d[3])
        : "r"(a[0]),"r"(a[1]),"r"(a[2]),"r"(a[3]), "r"(b[0]),"r"(b[1]));
}

// SW128 swizzle: 128B rows (64 fp16), 16B chunk c in 0..7
__device__ __forceinline__ uint32_t swz(int r, int c){
    return (uint32_t)(r*128 + ((c ^ (r&7))<<4));
}

// ---------------- generic 128x128 pipeline (K/Q proj, attn, out) ----------------
__device__ __forceinline__ void load_stage(uint32_t sb,
        const __half* Ah, int lda, const __half* Bh, int ldb, int k0, int tid)
{
    #pragma unroll
    for (int l = 0; l < 4; ++l){              // A: 128 rows x 8 chunks
        int idx = tid + l*THREADS;
        int r = idx >> 3, c = idx & 7;
        cp16(sb + swz(r, c), Ah + (size_t)r*lda + k0 + c*8);
    }
    #pragma unroll
    for (int l = 0; l < 4; ++l){              // B: 128 rows x 8 chunks
        int idx = tid + l*THREADS;
        int r = idx >> 3, c = idx & 7;
        cp16(sb + A_BYTES + swz(r, c), Bh + (size_t)r*ldb + k0 + c*8);
    }
}

__device__ __forceinline__ void load_frags(uint32_t sb, int kc, int lane,
                                           int wm, int wn,
                                           uint32_t a[2][4], uint32_t b[8][2])
{
    const int rw = lane & 7, tt = lane >> 3;
    #pragma unroll
    for (int mi = 0; mi < 2; ++mi){
        int row = wm*32 + mi*16 + rw + ((tt&1)<<3);
        int ch  = 2*kc + (tt>>1);
        ldsm4(sb + swz(row, ch), a[mi]);
    }
    #pragma unroll
    for (int jp = 0; jp < 4; ++jp){
        int row = wn*64 + jp*16 + rw + ((tt>>1)<<3);
        int ch  = 2*kc + (tt&1);
        uint32_t t4[4];
        ldsm4(sb + A_BYTES + swz(row, ch), t4);
        b[2*jp][0]=t4[0]; b[2*jp][1]=t4[1];
        b[2*jp+1][0]=t4[2]; b[2*jp+1][1]=t4[3];
    }
}

__device__ __forceinline__ void mma_burst(float acc[2][8][4],
                                          uint32_t a[2][4], uint32_t b[8][2])
{
    #pragma unroll
    for (int mi = 0; mi < 2; ++mi)
        #pragma unroll
        for (int nj = 0; nj < 8; ++nj)
            mma16816(acc[mi][nj], a[mi], b[nj]);
}

__device__ __forceinline__ void compute_stage(uint32_t sb, int lane,
                                              int wm, int wn, float acc[2][8][4])
{
    uint32_t a0[2][4], b0[8][2], a1[2][4], b1[8][2];
    load_frags(sb, 0, lane, wm, wn, a0, b0);
    load_frags(sb, 1, lane, wm, wn, a1, b1);
    mma_burst(acc, a0, b0);
    load_frags(sb, 2, lane, wm, wn, a0, b0);
    mma_burst(acc, a1, b1);
    load_frags(sb, 3, lane, wm, wn, a1, b1);
    mma_burst(acc, a0, b0);
    mma_burst(acc, a1, b1);
}

__device__ __forceinline__ void gemm_ml(const __half* Ah, int lda,
        const __half* Bh, int ldb, int niter, uint32_t su, float acc[2][8][4])
{
    const int tid = threadIdx.x;
    const int lane = tid & 31, w = tid >> 5, wm = w & 3, wn = w >> 2;
    load_stage(su,               Ah, lda, Bh, ldb, 0,  tid); CP_COMMIT();
    load_stage(su + STAGE_BYTES, Ah, lda, Bh, ldb, BK, tid); CP_COMMIT();
    for (int i = 0; i < niter; ++i){
        CP_WAIT1();
        __syncthreads();
        if (i + 2 < niter)
            load_stage(su + ((i+2)%3)*STAGE_BYTES, Ah, lda, Bh, ldb, (i+2)*BK, tid);
        CP_COMMIT();
        compute_stage(su + (i%3)*STAGE_BYTES, lane, wm, wn, acc);
    }
}

// ---------------- epilogue helpers ----------------
__device__ __forceinline__ void acc_to_sm(float* sm, int lane, int wm, int wn,
                                          float acc[2][8][4], bool transposed)
{
    #pragma unroll
    for (int mi = 0; mi < 2; ++mi)
        #pragma unroll
        for (int nj = 0; nj < 8; ++nj){
            int row = wm*32 + mi*16 + (lane>>2);
            int col = wn*64 + nj*8 + 2*(lane&3);
            if (!transposed){
                sm[row*PADL + col]     = acc[mi][nj][0];
                sm[row*PADL + col + 1] = acc[mi][nj][1];
                sm[(row+8)*PADL + col]     = acc[mi][nj][2];
                sm[(row+8)*PADL + col + 1] = acc[mi][nj][3];
            } else {
                sm[col*PADL + row]       = acc[mi][nj][0];
                sm[(col+1)*PADL + row]   = acc[mi][nj][1];
                sm[col*PADL + row + 8]   = acc[mi][nj][2];
                sm[(col+1)*PADL + row+8] = acc[mi][nj][3];
            }
        }
}

// ---------------- prep kernels ----------------
__global__ __launch_bounds__(256) void conv_x(const float* __restrict__ x){
    size_t i = ((size_t)blockIdx.x*256 + threadIdx.x)*4;
    float4 v = *(const float4*)(x + i);
    __half2* ph = (__half2*)(g_xh + i);
    ph[0] = __halves2half2(__float2half_rn(v.x), __float2half_rn(v.y));
    ph[1] = __halves2half2(__float2half_rn(v.z), __float2half_rn(v.w));
}
__global__ __launch_bounds__(256) void conv_w(const float* __restrict__ Wvr,
    const float* __restrict__ Wvi, const float* __restrict__ Wk, const float* __restrict__ Wq){
    size_t i = ((size_t)blockIdx.x*256 + threadIdx.x)*4;
    int w = (int)(i >> 20);
    size_t off = i & ((1u<<20)-1);
    const float* W = (w==0)?Wvr:(w==1)?Wvi:(w==2)?Wk:Wq;
    float4 v = *(const float4*)(W + off);
    __half2* ph = (__half2*)(g_Wh + i);
    ph[0] = __halves2half2(__float2half_rn(v.x), __float2half_rn(v.y));
    ph[1] = __halves2half2(__float2half_rn(v.z), __float2half_rn(v.w));
}

// ---------------- fused Vr+Vi projection + GLU gate ----------------
// block 128(M) x 64(N); both GEMMs share the A fragments; gate applied in
// registers; writes g_Vh directly (no fp32 round-trip, no smem epilogue).
__device__ __forceinline__ float gatef(float v){
    float sp = (v > 20.f) ? v : log1pf(expf(v));
    return tanhf(sp);
}
#define VA_BYTES 16384    // A 128x64 fp16
#define VB_BYTES 8192     // each B 64x64 fp16
#define VSTAGE (VA_BYTES + 2*VB_BYTES)   // 32768

__device__ __forceinline__ void load_stage_v(uint32_t sb, const __half* Ah,
        const __half* Bvr, const __half* Bvi, int k0, int tid)
{
    #pragma unroll
    for (int l = 0; l < 4; ++l){              // A: 128 rows x 8 chunks
        int idx = tid + l*THREADS;
        int r = idx >> 3, c = idx & 7;
        cp16(sb + swz(r, c), Ah + (size_t)r*DD + k0 + c*8);
    }
    #pragma unroll
    for (int l = 0; l < 2; ++l){              // Bvr: 64 rows x 8 chunks
        int idx = tid + l*THREADS;
        int r = idx >> 3, c = idx & 7;
        cp16(sb + VA_BYTES + swz(r, c), Bvr + (size_t)r*DD + k0 + c*8);
    }
    #pragma unroll
    for (int l = 0; l < 2; ++l){              // Bvi
        int idx = tid + l*THREADS;
        int r = idx >> 3, c = idx & 7;
        cp16(sb + VA_BYTES + VB_BYTES + swz(r, c), Bvi + (size_t)r*DD + k0 + c*8);
    }
}

__device__ __forceinline__ void compute_stage_v(uint32_t sb, int lane, int wm, int wn,
                                                float ar[2][4][4], float ai[2][4][4])
{
    const int rw = lane & 7, tt = lane >> 3;
    #pragma unroll
    for (int kc = 0; kc < 4; ++kc){
        uint32_t ah[2][4];
        #pragma unroll
        for (int mi = 0; mi < 2; ++mi){
            int row = wm*32 + mi*16 + rw + ((tt&1)<<3);
            int ch  = 2*kc + (tt>>1);
            ldsm4(sb + swz(row, ch), ah[mi]);
        }
        uint32_t br[4][2], bi[4][2];
        #pragma unroll
        for (int jp = 0; jp < 2; ++jp){
            int row = wn*32 + jp*16 + rw + ((tt>>1)<<3);
            int ch  = 2*kc + (tt&1);
            uint32_t t4[4];
            ldsm4(sb + VA_BYTES + swz(row, ch), t4);
            br[2*jp][0]=t4[0]; br[2*jp][1]=t4[1];
            br[2*jp+1][0]=t4[2]; br[2*jp+1][1]=t4[3];
            ldsm4(sb + VA_BYTES + VB_BYTES + swz(row, ch), t4);
            bi[2*jp][0]=t4[0]; bi[2*jp][1]=t4[1];
            bi[2*jp+1][0]=t4[2]; bi[2*jp+1][1]=t4[3];
        }
        #pragma unroll
        for (int mi = 0; mi < 2; ++mi)
            #pragma unroll
            for (int nj = 0; nj < 4; ++nj){
                mma16816(ar[mi][nj], ah[mi], br[nj]);
                mma16816(ai[mi][nj], ah[mi], bi[nj]);
            }
    }
}

// grid (16, 256): gn = x*64, m0 = y*128
__global__ __launch_bounds__(THREADS, 2) void proj_v(
    const float* __restrict__ bvr, const float* __restrict__ bvi)
{
    extern __shared__ char smem[];
    uint32_t su = smem_u32(smem);
    const int tid = threadIdx.x;
    const int lane = tid & 31, wrp = tid >> 5, wm = wrp & 3, wn = wrp >> 2;
    const int gn = blockIdx.x * 64;
    const int m0 = blockIdx.y * 128;

    const __half* Ah  = g_xh + (size_t)m0*DD;
    const __half* Bvr = g_Wh + (size_t)gn*DD;               // Wvr
    const __half* Bvi = g_Wh + (size_t)1*DD*DD + (size_t)gn*DD;

    float ar[2][4][4] = {}, ai[2][4][4] = {};
    load_stage_v(su,          Ah, Bvr, Bvi, 0,  tid); CP_COMMIT();
    load_stage_v(su + VSTAGE, Ah, Bvr, Bvi, BK, tid); CP_COMMIT();
    for (int i = 0; i < DD/BK; ++i){
        CP_WAIT1();
        __syncthreads();
        if (i + 2 < DD/BK)
            load_stage_v(su + ((i+2)%3)*VSTAGE, Ah, Bvr, Bvi, (i+2)*BK, tid);
        CP_COMMIT();
        compute_stage_v(su + (i%3)*VSTAGE, lane, wm, wn, ar, ai);
    }

    // register epilogue: bias + gate, direct half2 stores
    #pragma unroll
    for (int mi = 0; mi < 2; ++mi)
        #pragma unroll
        for (int nj = 0; nj < 4; ++nj){
            int col = gn + wn*32 + nj*8 + 2*(lane&3);
            float br0 = bvr[col], br1 = bvr[col+1];
            float bi0 = bvi[col], bi1 = bvi[col+1];
            int row = m0 + wm*32 + mi*16 + (lane>>2);
            float v0 = (ar[mi][nj][0]+br0) * gatef(ai[mi][nj][0]+bi0);
            float v1 = (ar[mi][nj][1]+br1) * gatef(ai[mi][nj][1]+bi1);
            *(__half2*)(g_Vh + (size_t)row*DD + col) =
                __halves2half2(__float2half_rn(v0), __float2half_rn(v1));
            float v2 = (ar[mi][nj][2]+br0) * gatef(ai[mi][nj][2]+bi0);
            float v3 = (ar[mi][nj][3]+br1) * gatef(ai[mi][nj][3]+bi1);
            *(__half2*)(g_Vh + (size_t)(row+8)*DD + col) =
                __halves2half2(__float2half_rn(v2), __float2half_rn(v3));
        }
}

// ---------------- projections: K, Q (transposed store) ----------------
// grid (16, 256): w = x>>3 in {0:K, 1:Q}, col block = (x&7)*128
__global__ __launch_bounds__(THREADS, 2) void proj_mma(
    const float* __restrict__ bk, const float* __restrict__ bq)
{
    extern __shared__ char smem[];
    uint32_t su = smem_u32(smem);
    const int tid = threadIdx.x;
    const int lane = tid & 31, wrp = tid >> 5, wm = wrp & 3, wn = wrp >> 2;
    const int w  = blockIdx.x >> 3;
    const int gn = (blockIdx.x & 7) * 128;
    const int m0 = blockIdx.y * 128;

    const __half* Ah = g_xh + (size_t)m0*DD;
    const __half* Bh = g_Wh + (size_t)(w+2)*DD*DD + (size_t)gn*DD;
    const float* bias = (w==0)?bk:bq;

    float acc[2][8][4] = {};
    gemm_ml(Ah, DD, Bh, DD, DD/BK, su, acc);
    __syncthreads();

    float* sm = (float*)smem;
    acc_to_sm(sm, lane, wm, wn, acc, true);   // sm[d][n]
    __syncthreads();
    __half* dst = (w==0) ? g_Kth : g_Qth;
    const int b = m0 >> 12, n0 = m0 & 4095;
    #pragma unroll
    for (int l = 0; l < 16; ++l){
        int idx = tid + l*THREADS;
        int d = idx >> 5, q = idx & 31;
        float bcol = bias[gn + d];
        float4 v = *(float4*)&sm[d*PADL + q*4];
        size_t go = ((size_t)b*DD + gn + d)*NSEQ + n0 + q*4;
        __half2* ph = (__half2*)(dst + go);
        ph[0] = __halves2half2(__float2half_rn(v.x + bcol), __float2half_rn(v.y + bcol));
        ph[1] = __halves2half2(__float2half_rn(v.z + bcol), __float2half_rn(v.w + bcol));
    }
}

// ---------------- norms ----------------
__global__ __launch_bounds__(256) void norm_kernel(){
    const __half* Ph = blockIdx.z ? g_Qth : g_Kth;
    float*        S  = blockIdx.z ? g_sQ  : g_sK;
    const int b = blockIdx.y;
    const int d = blockIdx.x*8 + (threadIdx.x >> 5);
    const int lane = threadIdx.x & 31;
    size_t base = ((size_t)b*DD + d)*NSEQ;
    const __half2* rh = (const __half2*)(Ph + base);
    float s = 0.f;
    for (int f = lane; f < NSEQ/2; f += 32){
        float2 h = __half22float2(rh[f]);
        s = fmaf(h.x, h.x, s); s = fmaf(h.y, h.y, s);
    }
    #pragma unroll
    for (int off = 16; off > 0; off >>= 1)
        s += __shfl_xor_sync(0xffffffffu, s, off);
    if (lane == 0) S[b*DD + d] = 1.f / (sqrtf(s) + 1e-5f);
}

// ---------------- feature attention ----------------
__device__ __forceinline__ float smuf(float v){
    return 0.5f * (1.25f*v + 0.75f*v*erff(750000.f*v));
}
__global__ __launch_bounds__(THREADS, 2) void attn_mma(){
    extern __shared__ char smem[];
    uint32_t su = smem_u32(smem);
    const int tid = threadIdx.x;
    const int lane = tid & 31, wrp = tid >> 5, wm = wrp & 3, wn = wrp >> 2;
    const int b  = blockIdx.z;
    const int e0 = blockIdx.y * 128;
    const int d0 = blockIdx.x * 128;

    size_t qa = ((size_t)b*DD + e0)*NSEQ;
    size_t ka = ((size_t)b*DD + d0)*NSEQ;
    float acc[2][8][4] = {};
    gemm_ml(g_Qth + qa, NSEQ, g_Kth + ka, NSEQ, NSEQ/BK, su, acc);
    __syncthreads();

    float* sm = (float*)smem;
    acc_to_sm(sm, lane, wm, wn, acc, false);   // sm[e][d]
    __syncthreads();
    const float* sQ = g_sQ + b*DD;
    const float* sK = g_sK + b*DD;
    #pragma unroll
    for (int l = 0; l < 16; ++l){
        int idx = tid + l*THREADS;
        int row = idx >> 5, q = idx & 31;
        float sq = sQ[e0 + row];
        float4 sk = *(const float4*)(sK + d0 + q*4);
        float4 v = *(float4*)&sm[row*PADL + q*4];
        v.x = smuf(v.x * sq * sk.x); v.y = smuf(v.y * sq * sk.y);
        v.z = smuf(v.z * sq * sk.z); v.w = smuf(v.w * sq * sk.w);
        size_t go = ((size_t)b*DD + e0 + row)*DD + d0 + q*4;
        __half2* ph = (__half2*)(g_Ath + go);
        ph[0] = __halves2half2(__float2half_rn(v.x), __float2half_rn(v.y));
        ph[1] = __halves2half2(__float2half_rn(v.z), __float2half_rn(v.w));
    }
}

// ---------------- output ----------------
__global__ __launch_bounds__(THREADS, 2) void out_mma(float* __restrict__ outp){
    extern __shared__ char smem[];
    uint32_t su = smem_u32(smem);
    const int tid = threadIdx.x;
    const int lane = tid & 31, wrp = tid >> 5, wm = wrp & 3, wn = wrp >> 2;
    const int m0 = blockIdx.y * 128;     // global token
    const int e0 = blockIdx.x * 128;
    const int b  = m0 >> 12;

    size_t va = (size_t)m0*DD;
    size_t aa = ((size_t)b*DD + e0)*DD;
    float acc[2][8][4] = {};
    gemm_ml(g_Vh + va, DD, g_Ath + aa, DD, DD/BK, su, acc);
    __syncthreads();

    float* sm = (float*)smem;
    acc_to_sm(sm, lane, wm, wn, acc, false);   // sm[n][e]
    __syncthreads();
    #pragma unroll
    for (int l = 0; l < 16; ++l){
        int idx = tid + l*THREADS;
        int row = idx >> 5, q = idx & 31;
        float4 v = *(float4*)&sm[row*PADL + q*4];
        *(float4*)(outp + (size_t)(m0+row)*DD + e0 + q*4) = v;
    }
}

// ---------------- launch ----------------
extern "C" void kernel_launch(void* const* d_in, const int* in_sizes, int n_in,
                              void* d_out, int out_size)
{
    const float* x   = (const float*)d_in[0];
    const float* Wvr = (const float*)d_in[1];
    const float* bvr = (const float*)d_in[2];
    const float* Wvi = (const float*)d_in[3];
    const float* bvi = (const float*)d_in[4];
    const float* Wk  = (const float*)d_in[5];
    const float* bk  = (const float*)d_in[6];
    const float* Wq  = (const float*)d_in[7];
    const float* bq  = (const float*)d_in[8];
    float* out = (float*)d_out;

    cudaFuncSetAttribute(proj_mma, cudaFuncAttributeMaxDynamicSharedMemorySize, SMEM_BYTES);
    cudaFuncSetAttribute(proj_v,   cudaFuncAttributeMaxDynamicSharedMemorySize, SMEM_BYTES);
    cudaFuncSetAttribute(attn_mma, cudaFuncAttributeMaxDynamicSharedMemorySize, SMEM_BYTES);
    cudaFuncSetAttribute(out_mma,  cudaFuncAttributeMaxDynamicSharedMemorySize, SMEM_BYTES);

    conv_x<<<BB*NSEQ*DD/(256*4), 256>>>(x);
    conv_w<<<4*DD*DD/(256*4), 256>>>(Wvr, Wvi, Wk, Wq);
    proj_mma<<<dim3(16, 256), THREADS, SMEM_BYTES>>>(bk, bq);
    proj_v<<<dim3(16, 256), THREADS, SMEM_BYTES>>>(bvr, bvi);
    norm_kernel<<<dim3(DD/8, BB, 2), 256>>>();
    attn_mma<<<dim3(8, 8, BB), THREADS, SMEM_BYTES>>>();
    out_mma<<<dim3(8, 256), THREADS, SMEM_BYTES>>>(out);
}

// round 16
// speedup vs baseline: 1.1146x; 1.0000x over previous
#include <cuda_runtime.h>
#include <cuda_fp16.h>
#include <math.h>
#include <stdint.h>

#define BB 8
#define NSEQ 4096
#define DD 1024

#define THREADS 256
#define BK 64
// attn/out: block 128x128x64, warp tile 32x64 (4 wm x 2 wn)
#define A_BYTES 16384               // 128*64*2
#define B_BYTES 16384
#define STAGE_BYTES (A_BYTES + B_BYTES)   // 32768
#define SMEM_BYTES (3*STAGE_BYTES)        // 98304 >= slab 67584
#define PADL 132                    // fp32 epilogue slab row stride

// ---------------- scratch (all single fp16) ----------------
__device__ __half g_xh[BB*NSEQ*DD];
__device__ __half g_Wh[4*DD*DD];
__device__ __half g_Vh[BB*NSEQ*DD];
__device__ __half g_Kth[BB*DD*NSEQ];   // [b][d][n]
__device__ __half g_Qth[BB*DD*NSEQ];   // [b][e][n]
__device__ __half g_Ath[BB*DD*DD];     // [b][e][d]
__device__ float  g_sK[BB*DD], g_sQ[BB*DD];

// ---------------- asm helpers ----------------
__device__ __forceinline__ uint32_t smem_u32(const void* p){
    uint32_t a;
    asm("{ .reg .u64 t; cvta.to.shared.u64 t, %1; cvt.u32.u64 %0, t; }"
        : "=r"(a) : "l"(p));
    return a;
}
__device__ __forceinline__ void cp16(uint32_t s, const void* g){
    asm volatile("cp.async.cg.shared.global [%0], [%1], 16;"
                 :: "r"(s), "l"(__cvta_generic_to_global(g)) : "memory");
}
#define CP_COMMIT() asm volatile("cp.async.commit_group;" ::: "memory")
#define CP_WAIT1()  asm volatile("cp.async.wait_group 1;" ::: "memory")

__device__ __forceinline__ void ldsm4(uint32_t addr, uint32_t* r){
    asm volatile("ldmatrix.sync.aligned.m8n8.x4.shared.b16 {%0,%1,%2,%3}, [%4];"
        : "=r"(r[0]),"=r"(r[1]),"=r"(r[2]),"=r"(r[3]) : "r"(addr));
}
__device__ __forceinline__ void mma16816(float* d, const uint32_t* a, const uint32_t* b){
    asm volatile("mma.sync.aligned.m16n8k16.row.col.f32.f16.f16.f32 "
        "{%0,%1,%2,%3}, {%4,%5,%6,%7}, {%8,%9}, {%0,%1,%2,%3};"
        : "+f"(d[0]),"+f"(d[1]),"+f"(d[2]),"+f"(d[3])
        : "r"(a[0]),"r"(a[1]),"r"(a[2]),"r"(a[3]), "r"(b[0]),"r"(b[1]));
}

// SW128 swizzle: 128B rows (64 fp16), 16B chunk c in 0..7
__device__ __forceinline__ uint32_t swz(int r, int c){
    return (uint32_t)(r*128 + ((c ^ (r&7))<<4));
}

// ---------------- generic 128x128 pipeline (attn, out) ----------------
__device__ __forceinline__ void load_stage(uint32_t sb,
        const __half* Ah, int lda, const __half* Bh, int ldb, int k0, int tid)
{
    #pragma unroll
    for (int l = 0; l < 4; ++l){
        int idx = tid + l*THREADS;
        int r = idx >> 3, c = idx & 7;
        cp16(sb + swz(r, c), Ah + (size_t)r*lda + k0 + c*8);
    }
    #pragma unroll
    for (int l = 0; l < 4; ++l){
        int idx = tid + l*THREADS;
        int r = idx >> 3, c = idx & 7;
        cp16(sb + A_BYTES + swz(r, c), Bh + (size_t)r*ldb + k0 + c*8);
    }
}

__device__ __forceinline__ void load_frags(uint32_t sb, int kc, int lane,
                                           int wm, int wn,
                                           uint32_t a[2][4], uint32_t b[8][2])
{
    const int rw = lane & 7, tt = lane >> 3;
    #pragma unroll
    for (int mi = 0; mi < 2; ++mi){
        int row = wm*32 + mi*16 + rw + ((tt&1)<<3);
        int ch  = 2*kc + (tt>>1);
        ldsm4(sb + swz(row, ch), a[mi]);
    }
    #pragma unroll
    for (int jp = 0; jp < 4; ++jp){
        int row = wn*64 + jp*16 + rw + ((tt>>1)<<3);
        int ch  = 2*kc + (tt&1);
        uint32_t t4[4];
        ldsm4(sb + A_BYTES + swz(row, ch), t4);
        b[2*jp][0]=t4[0]; b[2*jp][1]=t4[1];
        b[2*jp+1][0]=t4[2]; b[2*jp+1][1]=t4[3];
    }
}

__device__ __forceinline__ void mma_burst(float acc[2][8][4],
                                          uint32_t a[2][4], uint32_t b[8][2])
{
    #pragma unroll
    for (int mi = 0; mi < 2; ++mi)
        #pragma unroll
        for (int nj = 0; nj < 8; ++nj)
            mma16816(acc[mi][nj], a[mi], b[nj]);
}

__device__ __forceinline__ void compute_stage(uint32_t sb, int lane,
                                              int wm, int wn, float acc[2][8][4])
{
    uint32_t a0[2][4], b0[8][2], a1[2][4], b1[8][2];
    load_frags(sb, 0, lane, wm, wn, a0, b0);
    load_frags(sb, 1, lane, wm, wn, a1, b1);
    mma_burst(acc, a0, b0);
    load_frags(sb, 2, lane, wm, wn, a0, b0);
    mma_burst(acc, a1, b1);
    load_frags(sb, 3, lane, wm, wn, a1, b1);
    mma_burst(acc, a0, b0);
    mma_burst(acc, a1, b1);
}

__device__ __forceinline__ void gemm_ml(const __half* Ah, int lda,
        const __half* Bh, int ldb, int niter, uint32_t su, float acc[2][8][4])
{
    const int tid = threadIdx.x;
    const int lane = tid & 31, w = tid >> 5, wm = w & 3, wn = w >> 2;
    load_stage(su,               Ah, lda, Bh, ldb, 0,  tid); CP_COMMIT();
    load_stage(su + STAGE_BYTES, Ah, lda, Bh, ldb, BK, tid); CP_COMMIT();
    for (int i = 0; i < niter; ++i){
        CP_WAIT1();
        __syncthreads();
        if (i + 2 < niter)
            load_stage(su + ((i+2)%3)*STAGE_BYTES, Ah, lda, Bh, ldb, (i+2)*BK, tid);
        CP_COMMIT();
        compute_stage(su + (i%3)*STAGE_BYTES, lane, wm, wn, acc);
    }
}

// ---------------- epilogue helpers ----------------
__device__ __forceinline__ void acc_to_sm(float* sm, int lane, int wm, int wn,
                                          float acc[2][8][4], bool transposed)
{
    #pragma unroll
    for (int mi = 0; mi < 2; ++mi)
        #pragma unroll
        for (int nj = 0; nj < 8; ++nj){
            int row = wm*32 + mi*16 + (lane>>2);
            int col = wn*64 + nj*8 + 2*(lane&3);
            if (!transposed){
                sm[row*PADL + col]     = acc[mi][nj][0];
                sm[row*PADL + col + 1] = acc[mi][nj][1];
                sm[(row+8)*PADL + col]     = acc[mi][nj][2];
                sm[(row+8)*PADL + col + 1] = acc[mi][nj][3];
            } else {
                sm[col*PADL + row]       = acc[mi][nj][0];
                sm[(col+1)*PADL + row]   = acc[mi][nj][1];
                sm[col*PADL + row + 8]   = acc[mi][nj][2];
                sm[(col+1)*PADL + row+8] = acc[mi][nj][3];
            }
        }
}

// transposed slab store for 128M x 64N warp-tiled acc (proj_kq):
// sm[d_local][m], d_local = wn*32 + nj*8 + 2*(lane&3), m = wm*32 + mi*16 + ...
__device__ __forceinline__ void acc_to_sm_t64(float* sm, int lane, int wm, int wn,
                                              float acc[2][4][4])
{
    #pragma unroll
    for (int mi = 0; mi < 2; ++mi)
        #pragma unroll
        for (int nj = 0; nj < 4; ++nj){
            int row = wm*32 + mi*16 + (lane>>2);
            int col = wn*32 + nj*8 + 2*(lane&3);
            sm[col*PADL + row]       = acc[mi][nj][0];
            sm[(col+1)*PADL + row]   = acc[mi][nj][1];
            sm[col*PADL + row + 8]   = acc[mi][nj][2];
            sm[(col+1)*PADL + row+8] = acc[mi][nj][3];
        }
}

// ---------------- prep kernels ----------------
__global__ __launch_bounds__(256) void conv_x(const float* __restrict__ x){
    size_t i = ((size_t)blockIdx.x*256 + threadIdx.x)*4;
    float4 v = *(const float4*)(x + i);
    __half2* ph = (__half2*)(g_xh + i);
    ph[0] = __halves2half2(__float2half_rn(v.x), __float2half_rn(v.y));
    ph[1] = __halves2half2(__float2half_rn(v.z), __float2half_rn(v.w));
}
__global__ __launch_bounds__(256) void conv_w(const float* __restrict__ Wvr,
    const float* __restrict__ Wvi, const float* __restrict__ Wk, const float* __restrict__ Wq){
    size_t i = ((size_t)blockIdx.x*256 + threadIdx.x)*4;
    int w = (int)(i >> 20);
    size_t off = i & ((1u<<20)-1);
    const float* W = (w==0)?Wvr:(w==1)?Wvi:(w==2)?Wk:Wq;
    float4 v = *(const float4*)(W + off);
    __half2* ph = (__half2*)(g_Wh + i);
    ph[0] = __halves2half2(__float2half_rn(v.x), __float2half_rn(v.y));
    ph[1] = __halves2half2(__float2half_rn(v.z), __float2half_rn(v.w));
}

// ---------------- shared dual-GEMM pipeline (128M x 64N, two B matrices) ----
#define VA_BYTES 16384    // A 128x64 fp16
#define VB_BYTES 8192     // each B 64x64 fp16
#define VSTAGE (VA_BYTES + 2*VB_BYTES)   // 32768

__device__ __forceinline__ void load_stage_2b(uint32_t sb, const __half* Ah,
        const __half* B0, const __half* B1, int k0, int tid)
{
    #pragma unroll
    for (int l = 0; l < 4; ++l){
        int idx = tid + l*THREADS;
        int r = idx >> 3, c = idx & 7;
        cp16(sb + swz(r, c), Ah + (size_t)r*DD + k0 + c*8);
    }
    #pragma unroll
    for (int l = 0; l < 2; ++l){
        int idx = tid + l*THREADS;
        int r = idx >> 3, c = idx & 7;
        cp16(sb + VA_BYTES + swz(r, c), B0 + (size_t)r*DD + k0 + c*8);
    }
    #pragma unroll
    for (int l = 0; l < 2; ++l){
        int idx = tid + l*THREADS;
        int r = idx >> 3, c = idx & 7;
        cp16(sb + VA_BYTES + VB_BYTES + swz(r, c), B1 + (size_t)r*DD + k0 + c*8);
    }
}

__device__ __forceinline__ void compute_stage_2b(uint32_t sb, int lane, int wm, int wn,
                                                 float a0[2][4][4], float a1[2][4][4])
{
    const int rw = lane & 7, tt = lane >> 3;
    #pragma unroll
    for (int kc = 0; kc < 4; ++kc){
        uint32_t ah[2][4];
        #pragma unroll
        for (int mi = 0; mi < 2; ++mi){
            int row = wm*32 + mi*16 + rw + ((tt&1)<<3);
            int ch  = 2*kc + (tt>>1);
            ldsm4(sb + swz(row, ch), ah[mi]);
        }
        uint32_t b0[4][2], b1[4][2];
        #pragma unroll
        for (int jp = 0; jp < 2; ++jp){
            int row = wn*32 + jp*16 + rw + ((tt>>1)<<3);
            int ch  = 2*kc + (tt&1);
            uint32_t t4[4];
            ldsm4(sb + VA_BYTES + swz(row, ch), t4);
            b0[2*jp][0]=t4[0]; b0[2*jp][1]=t4[1];
            b0[2*jp+1][0]=t4[2]; b0[2*jp+1][1]=t4[3];
            ldsm4(sb + VA_BYTES + VB_BYTES + swz(row, ch), t4);
            b1[2*jp][0]=t4[0]; b1[2*jp][1]=t4[1];
            b1[2*jp+1][0]=t4[2]; b1[2*jp+1][1]=t4[3];
        }
        #pragma unroll
        for (int mi = 0; mi < 2; ++mi)
            #pragma unroll
            for (int nj = 0; nj < 4; ++nj){
                mma16816(a0[mi][nj], ah[mi], b0[nj]);
                mma16816(a1[mi][nj], ah[mi], b1[nj]);
            }
    }
}

__device__ __forceinline__ void gemm_ml_2b(const __half* Ah,
        const __half* B0, const __half* B1, uint32_t su,
        float a0[2][4][4], float a1[2][4][4])
{
    const int tid = threadIdx.x;
    const int lane = tid & 31, w = tid >> 5, wm = w & 3, wn = w >> 2;
    load_stage_2b(su,          Ah, B0, B1, 0,  tid); CP_COMMIT();
    load_stage_2b(su + VSTAGE, Ah, B0, B1, BK, tid); CP_COMMIT();
    for (int i = 0; i < DD/BK; ++i){
        CP_WAIT1();
        __syncthreads();
        if (i + 2 < DD/BK)
            load_stage_2b(su + ((i+2)%3)*VSTAGE, Ah, B0, B1, (i+2)*BK, tid);
        CP_COMMIT();
        compute_stage_2b(su + (i%3)*VSTAGE, lane, wm, wn, a0, a1);
    }
}

// ---------------- fused Vr+Vi projection + GLU gate ----------------
__device__ __forceinline__ float gatef(float v){
    float sp = (v > 20.f) ? v : log1pf(expf(v));
    return tanhf(sp);
}
// grid (16, 256): gn = x*64, m0 = y*128
__global__ __launch_bounds__(THREADS, 2) void proj_v(
    const float* __restrict__ bvr, const float* __restrict__ bvi)
{
    extern __shared__ char smem[];
    uint32_t su = smem_u32(smem);
    const int tid = threadIdx.x;
    const int lane = tid & 31, wrp = tid >> 5, wm = wrp & 3, wn = wrp >> 2;
    const int gn = blockIdx.x * 64;
    const int m0 = blockIdx.y * 128;

    const __half* Ah  = g_xh + (size_t)m0*DD;
    const __half* Bvr = g_Wh + (size_t)gn*DD;
    const __half* Bvi = g_Wh + (size_t)1*DD*DD + (size_t)gn*DD;

    float ar[2][4][4] = {}, ai[2][4][4] = {};
    gemm_ml_2b(Ah, Bvr, Bvi, su, ar, ai);

    #pragma unroll
    for (int mi = 0; mi < 2; ++mi)
        #pragma unroll
        for (int nj = 0; nj < 4; ++nj){
            int col = gn + wn*32 + nj*8 + 2*(lane&3);
            float br0 = bvr[col], br1 = bvr[col+1];
            float bi0 = bvi[col], bi1 = bvi[col+1];
            int row = m0 + wm*32 + mi*16 + (lane>>2);
            float v0 = (ar[mi][nj][0]+br0) * gatef(ai[mi][nj][0]+bi0);
            float v1 = (ar[mi][nj][1]+br1) * gatef(ai[mi][nj][1]+bi1);
            *(__half2*)(g_Vh + (size_t)row*DD + col) =
                __halves2half2(__float2half_rn(v0), __float2half_rn(v1));
            float v2 = (ar[mi][nj][2]+br0) * gatef(ai[mi][nj][2]+bi0);
            float v3 = (ar[mi][nj][3]+br1) * gatef(ai[mi][nj][3]+bi1);
            *(__half2*)(g_Vh + (size_t)(row+8)*DD + col) =
                __halves2half2(__float2half_rn(v2), __float2half_rn(v3));
        }
}

// ---------------- fused K+Q projection (shared A, transposed store) --------
// grid (16, 256): gn = x*64, m0 = y*128
__global__ __launch_bounds__(THREADS, 2) void proj_kq(
    const float* __restrict__ bk, const float* __restrict__ bq)
{
    extern __shared__ char smem[];
    uint32_t su = smem_u32(smem);
    const int tid = threadIdx.x;
    const int lane = tid & 31, wrp = tid >> 5, wm = wrp & 3, wn = wrp >> 2;
    const int gn = blockIdx.x * 64;
    const int m0 = blockIdx.y * 128;

    const __half* Ah = g_xh + (size_t)m0*DD;
    const __half* Bk = g_Wh + (size_t)2*DD*DD + (size_t)gn*DD;
    const __half* Bq = g_Wh + (size_t)3*DD*DD + (size_t)gn*DD;

    float ak[2][4][4] = {}, aq[2][4][4] = {};
    gemm_ml_2b(Ah, Bk, Bq, su, ak, aq);

    float* sm = (float*)smem;
    const int b = m0 >> 12, n0 = m0 & 4095;
    // pass 0: K, pass 1: Q
    #pragma unroll
    for (int p = 0; p < 2; ++p){
        __syncthreads();
        acc_to_sm_t64(sm, lane, wm, wn, p ? aq : ak);   // sm[d_local][m]
        __syncthreads();
        __half* dst = p ? g_Qth : g_Kth;
        const float* bias = p ? bq : bk;
        #pragma unroll
        for (int l = 0; l < 8; ++l){
            int idx = tid + l*THREADS;     // 2048 = 64 d x 32 q
            int d = idx >> 5, q = idx & 31;
            float bcol = bias[gn + d];
            float4 v = *(float4*)&sm[d*PADL + q*4];
            size_t go = ((size_t)b*DD + gn + d)*NSEQ + n0 + q*4;
            __half2* ph = (__half2*)(dst + go);
            ph[0] = __halves2half2(__float2half_rn(v.x + bcol), __float2half_rn(v.y + bcol));
            ph[1] = __halves2half2(__float2half_rn(v.z + bcol), __float2half_rn(v.w + bcol));
        }
    }
}

// ---------------- norms ----------------
__global__ __launch_bounds__(256) void norm_kernel(){
    const __half* Ph = blockIdx.z ? g_Qth : g_Kth;
    float*        S  = blockIdx.z ? g_sQ  : g_sK;
    const int b = blockIdx.y;
    const int d = blockIdx.x*8 + (threadIdx.x >> 5);
    const int lane = threadIdx.x & 31;
    size_t base = ((size_t)b*DD + d)*NSEQ;
    const __half2* rh = (const __half2*)(Ph + base);
    float s = 0.f;
    for (int f = lane; f < NSEQ/2; f += 32){
        float2 h = __half22float2(rh[f]);
        s = fmaf(h.x, h.x, s); s = fmaf(h.y, h.y, s);
    }
    #pragma unroll
    for (int off = 16; off > 0; off >>= 1)
        s += __shfl_xor_sync(0xffffffffu, s, off);
    if (lane == 0) S[b*DD + d] = 1.f / (sqrtf(s) + 1e-5f);
}

// ---------------- feature attention ----------------
__device__ __forceinline__ float smuf(float v){
    return 0.5f * (1.25f*v + 0.75f*v*erff(750000.f*v));
}
__global__ __launch_bounds__(THREADS, 2) void attn_mma(){
    extern __shared__ char smem[];
    uint32_t su = smem_u32(smem);
    const int tid = threadIdx.x;
    const int lane = tid & 31, wrp = tid >> 5, wm = wrp & 3, wn = wrp >> 2;
    const int b  = blockIdx.z;
    const int e0 = blockIdx.y * 128;
    const int d0 = blockIdx.x * 128;

    size_t qa = ((size_t)b*DD + e0)*NSEQ;
    size_t ka = ((size_t)b*DD + d0)*NSEQ;
    float acc[2][8][4] = {};
    gemm_ml(g_Qth + qa, NSEQ, g_Kth + ka, NSEQ, NSEQ/BK, su, acc);
    __syncthreads();

    float* sm = (float*)smem;
    acc_to_sm(sm, lane, wm, wn, acc, false);   // sm[e][d]
    __syncthreads();
    const float* sQ = g_sQ + b*DD;
    const float* sK = g_sK + b*DD;
    #pragma unroll
    for (int l = 0; l < 16; ++l){
        int idx = tid + l*THREADS;
        int row = idx >> 5, q = idx & 31;
        float sq = sQ[e0 + row];
        float4 sk = *(const float4*)(sK + d0 + q*4);
        float4 v = *(float4*)&sm[row*PADL + q*4];
        v.x = smuf(v.x * sq * sk.x); v.y = smuf(v.y * sq * sk.y);
        v.z = smuf(v.z * sq * sk.z); v.w = smuf(v.w * sq * sk.w);
        size_t go = ((size_t)b*DD + e0 + row)*DD + d0 + q*4;
        __half2* ph = (__half2*)(g_Ath + go);
        ph[0] = __halves2half2(__float2half_rn(v.x), __float2half_rn(v.y));
        ph[1] = __halves2half2(__float2half_rn(v.z), __float2half_rn(v.w));
    }
}

// ---------------- output ----------------
__global__ __launch_bounds__(THREADS, 2) void out_mma(float* __restrict__ outp){
    extern __shared__ char smem[];
    uint32_t su = smem_u32(smem);
    const int tid = threadIdx.x;
    const int lane = tid & 31, wrp = tid >> 5, wm = wrp & 3, wn = wrp >> 2;
    const int m0 = blockIdx.y * 128;     // global token
    const int e0 = blockIdx.x * 128;
    const int b  = m0 >> 12;

    size_t va = (size_t)m0*DD;
    size_t aa = ((size_t)b*DD + e0)*DD;
    float acc[2][8][4] = {};
    gemm_ml(g_Vh + va, DD, g_Ath + aa, DD, DD/BK, su, acc);
    __syncthreads();

    float* sm = (float*)smem;
    acc_to_sm(sm, lane, wm, wn, acc, false);   // sm[n][e]
    __syncthreads();
    #pragma unroll
    for (int l = 0; l < 16; ++l){
        int idx = tid + l*THREADS;
        int row = idx >> 5, q = idx & 31;
        float4 v = *(float4*)&sm[row*PADL + q*4];
        *(float4*)(outp + (size_t)(m0+row)*DD + e0 + q*4) = v;
    }
}

// ---------------- launch ----------------
extern "C" void kernel_launch(void* const* d_in, const int* in_sizes, int n_in,
                              void* d_out, int out_size)
{
    const float* x   = (const float*)d_in[0];
    const float* Wvr = (const float*)d_in[1];
    const float* bvr = (const float*)d_in[2];
    const float* Wvi = (const float*)d_in[3];
    const float* bvi = (const float*)d_in[4];
    const float* Wk  = (const float*)d_in[5];
    const float* bk  = (const float*)d_in[6];
    const float* Wq  = (const float*)d_in[7];
    const float* bq  = (const float*)d_in[8];
    float* out = (float*)d_out;

    cudaFuncSetAttribute(proj_kq,  cudaFuncAttributeMaxDynamicSharedMemorySize, SMEM_BYTES);
    cudaFuncSetAttribute(proj_v,   cudaFuncAttributeMaxDynamicSharedMemorySize, SMEM_BYTES);
    cudaFuncSetAttribute(attn_mma, cudaFuncAttributeMaxDynamicSharedMemorySize, SMEM_BYTES);
    cudaFuncSetAttribute(out_mma,  cudaFuncAttributeMaxDynamicSharedMemorySize, SMEM_BYTES);

    conv_x<<<BB*NSEQ*DD/(256*4), 256>>>(x);
    conv_w<<<4*DD*DD/(256*4), 256>>>(Wvr, Wvi, Wk, Wq);
    proj_kq<<<dim3(16, 256), THREADS, SMEM_BYTES>>>(bk, bq);
    proj_v<<<dim3(16, 256), THREADS, SMEM_BYTES>>>(bvr, bvi);
    norm_kernel<<<dim3(DD/8, BB, 2), 256>>>();
    attn_mma<<<dim3(8, 8, BB), THREADS, SMEM_BYTES>>>();
    out_mma<<<dim3(8, 256), THREADS, SMEM_BYTES>>>(out);
}

// round 17
// speedup vs baseline: 1.1286x; 1.0126x over previous
#include <cuda_runtime.h>
#include <cuda_fp16.h>
#include <math.h>
#include <stdint.h>

#define BB 8
#define NSEQ 4096
#define DD 1024

#define THREADS 256
#define BK 64
#define A_BYTES 16384               // 128*64*2
#define B_BYTES 16384
#define STAGE_BYTES (A_BYTES + B_BYTES)   // 32768
#define SMEM_BYTES (3*STAGE_BYTES)        // 98304
#define PADL 132

// ---------------- scratch ----------------
__device__ __half g_xh[BB*NSEQ*DD];
__device__ __half g_Wh[4*DD*DD];
__device__ __half g_Vh[BB*NSEQ*DD];
__device__ __half g_Kth[BB*DD*NSEQ];   // [b][d][n]
__device__ __half g_Qth[BB*DD*NSEQ];   // [b][e][n]
__device__ __half g_Ath[BB*DD*DD];     // [b][e][d]
__device__ float  g_nsK[BB*DD], g_nsQ[BB*DD];   // sum of squares (atomic)
__device__ float  g_sK[BB*DD], g_sQ[BB*DD];     // 1/(sqrt+eps)

// ---------------- asm helpers ----------------
__device__ __forceinline__ uint32_t smem_u32(const void* p){
    uint32_t a;
    asm("{ .reg .u64 t; cvta.to.shared.u64 t, %1; cvt.u32.u64 %0, t; }"
        : "=r"(a) : "l"(p));
    return a;
}
__device__ __forceinline__ void cp16(uint32_t s, const void* g){
    asm volatile("cp.async.cg.shared.global [%0], [%1], 16;"
                 :: "r"(s), "l"(__cvta_generic_to_global(g)) : "memory");
}
#define CP_COMMIT() asm volatile("cp.async.commit_group;" ::: "memory")
#define CP_WAIT1()  asm volatile("cp.async.wait_group 1;" ::: "memory")

__device__ __forceinline__ void ldsm4(uint32_t addr, uint32_t* r){
    asm volatile("ldmatrix.sync.aligned.m8n8.x4.shared.b16 {%0,%1,%2,%3}, [%4];"
        : "=r"(r[0]),"=r"(r[1]),"=r"(r[2]),"=r"(r[3]) : "r"(addr));
}
__device__ __forceinline__ void mma16816(float* d, const uint32_t* a, const uint32_t* b){
    asm volatile("mma.sync.aligned.m16n8k16.row.col.f32.f16.f16.f32 "
        "{%0,%1,%2,%3}, {%4,%5,%6,%7}, {%8,%9}, {%0,%1,%2,%3};"
        : "+f"(d[0]),"+f"(d[1]),"+f"(d[2]),"+f"(d[3])
        : "r"(a[0]),"r"(a[1]),"r"(a[2]),"r"(a[3]), "r"(b[0]),"r"(b[1]));
}

__device__ __forceinline__ uint32_t swz(int r, int c){
    return (uint32_t)(r*128 + ((c ^ (r&7))<<4));
}

// ---------------- generic 128x128 pipeline (attn, out) ----------------
__device__ __forceinline__ void load_stage(uint32_t sb,
        const __half* Ah, int lda, const __half* Bh, int ldb, int k0, int tid)
{
    #pragma unroll
    for (int l = 0; l < 4; ++l){
        int idx = tid + l*THREADS;
        int r = idx >> 3, c = idx & 7;
        cp16(sb + swz(r, c), Ah + (size_t)r*lda + k0 + c*8);
    }
    #pragma unroll
    for (int l = 0; l < 4; ++l){
        int idx = tid + l*THREADS;
        int r = idx >> 3, c = idx & 7;
        cp16(sb + A_BYTES + swz(r, c), Bh + (size_t)r*ldb + k0 + c*8);
    }
}

__device__ __forceinline__ void load_frags(uint32_t sb, int kc, int lane,
                                           int wm, int wn,
                                           uint32_t a[2][4], uint32_t b[8][2])
{
    const int rw = lane & 7, tt = lane >> 3;
    #pragma unroll
    for (int mi = 0; mi < 2; ++mi){
        int row = wm*32 + mi*16 + rw + ((tt&1)<<3);
        int ch  = 2*kc + (tt>>1);
        ldsm4(sb + swz(row, ch), a[mi]);
    }
    #pragma unroll
    for (int jp = 0; jp < 4; ++jp){
        int row = wn*64 + jp*16 + rw + ((tt>>1)<<3);
        int ch  = 2*kc + (tt&1);
        uint32_t t4[4];
        ldsm4(sb + A_BYTES + swz(row, ch), t4);
        b[2*jp][0]=t4[0]; b[2*jp][1]=t4[1];
        b[2*jp+1][0]=t4[2]; b[2*jp+1][1]=t4[3];
    }
}

__device__ __forceinline__ void mma_burst(float acc[2][8][4],
                                          uint32_t a[2][4], uint32_t b[8][2])
{
    #pragma unroll
    for (int mi = 0; mi < 2; ++mi)
        #pragma unroll
        for (int nj = 0; nj < 8; ++nj)
            mma16816(acc[mi][nj], a[mi], b[nj]);
}

__device__ __forceinline__ void compute_stage(uint32_t sb, int lane,
                                              int wm, int wn, float acc[2][8][4])
{
    uint32_t a0[2][4], b0[8][2], a1[2][4], b1[8][2];
    load_frags(sb, 0, lane, wm, wn, a0, b0);
    load_frags(sb, 1, lane, wm, wn, a1, b1);
    mma_burst(acc, a0, b0);
    load_frags(sb, 2, lane, wm, wn, a0, b0);
    mma_burst(acc, a1, b1);
    load_frags(sb, 3, lane, wm, wn, a1, b1);
    mma_burst(acc, a0, b0);
    mma_burst(acc, a1, b1);
}

__device__ __forceinline__ void gemm_ml(const __half* Ah, int lda,
        const __half* Bh, int ldb, int niter, uint32_t su, float acc[2][8][4])
{
    const int tid = threadIdx.x;
    const int lane = tid & 31, w = tid >> 5, wm = w & 3, wn = w >> 2;
    load_stage(su,               Ah, lda, Bh, ldb, 0,  tid); CP_COMMIT();
    load_stage(su + STAGE_BYTES, Ah, lda, Bh, ldb, BK, tid); CP_COMMIT();
    for (int i = 0; i < niter; ++i){
        CP_WAIT1();
        __syncthreads();
        if (i + 2 < niter)
            load_stage(su + ((i+2)%3)*STAGE_BYTES, Ah, lda, Bh, ldb, (i+2)*BK, tid);
        CP_COMMIT();
        compute_stage(su + (i%3)*STAGE_BYTES, lane, wm, wn, acc);
    }
}

// transposed slab store for 128M x 64N warp-tiled acc (proj_kq)
__device__ __forceinline__ void acc_to_sm_t64(float* sm, int lane, int wm, int wn,
                                              float acc[2][4][4])
{
    #pragma unroll
    for (int mi = 0; mi < 2; ++mi)
        #pragma unroll
        for (int nj = 0; nj < 4; ++nj){
            int row = wm*32 + mi*16 + (lane>>2);
            int col = wn*32 + nj*8 + 2*(lane&3);
            sm[col*PADL + row]       = acc[mi][nj][0];
            sm[(col+1)*PADL + row]   = acc[mi][nj][1];
            sm[col*PADL + row + 8]   = acc[mi][nj][2];
            sm[(col+1)*PADL + row+8] = acc[mi][nj][3];
        }
}

// ---------------- prep kernels ----------------
__global__ __launch_bounds__(256) void conv_x(const float* __restrict__ x){
    size_t i = ((size_t)blockIdx.x*256 + threadIdx.x)*4;
    float4 v = *(const float4*)(x + i);
    __half2* ph = (__half2*)(g_xh + i);
    ph[0] = __halves2half2(__float2half_rn(v.x), __float2half_rn(v.y));
    ph[1] = __halves2half2(__float2half_rn(v.z), __float2half_rn(v.w));
}
__global__ __launch_bounds__(256) void conv_w(const float* __restrict__ Wvr,
    const float* __restrict__ Wvi, const float* __restrict__ Wk, const float* __restrict__ Wq){
    size_t i = ((size_t)blockIdx.x*256 + threadIdx.x)*4;
    int w = (int)(i >> 20);
    size_t off = i & ((1u<<20)-1);
    const float* W = (w==0)?Wvr:(w==1)?Wvi:(w==2)?Wk:Wq;
    float4 v = *(const float4*)(W + off);
    __half2* ph = (__half2*)(g_Wh + i);
    ph[0] = __halves2half2(__float2half_rn(v.x), __float2half_rn(v.y));
    ph[1] = __halves2half2(__float2half_rn(v.z), __float2half_rn(v.w));
}
__global__ __launch_bounds__(256) void zero_ns(){
    int i = blockIdx.x*256 + threadIdx.x;
    g_nsK[i] = 0.f; g_nsQ[i] = 0.f;
}
__global__ __launch_bounds__(256) void fin_ns(){
    int i = blockIdx.x*256 + threadIdx.x;
    g_sK[i] = 1.f / (sqrtf(g_nsK[i]) + 1e-5f);
    g_sQ[i] = 1.f / (sqrtf(g_nsQ[i]) + 1e-5f);
}

// ---------------- shared dual-GEMM pipeline (128M x 64N, two B matrices) ----
#define VA_BYTES 16384
#define VB_BYTES 8192
#define VSTAGE (VA_BYTES + 2*VB_BYTES)   // 32768

__device__ __forceinline__ void load_stage_2b(uint32_t sb, const __half* Ah,
        const __half* B0, const __half* B1, int k0, int tid)
{
    #pragma unroll
    for (int l = 0; l < 4; ++l){
        int idx = tid + l*THREADS;
        int r = idx >> 3, c = idx & 7;
        cp16(sb + swz(r, c), Ah + (size_t)r*DD + k0 + c*8);
    }
    #pragma unroll
    for (int l = 0; l < 2; ++l){
        int idx = tid + l*THREADS;
        int r = idx >> 3, c = idx & 7;
        cp16(sb + VA_BYTES + swz(r, c), B0 + (size_t)r*DD + k0 + c*8);
    }
    #pragma unroll
    for (int l = 0; l < 2; ++l){
        int idx = tid + l*THREADS;
        int r = idx >> 3, c = idx & 7;
        cp16(sb + VA_BYTES + VB_BYTES + swz(r, c), B1 + (size_t)r*DD + k0 + c*8);
    }
}

__device__ __forceinline__ void compute_stage_2b(uint32_t sb, int lane, int wm, int wn,
                                                 float a0[2][4][4], float a1[2][4][4])
{
    const int rw = lane & 7, tt = lane >> 3;
    #pragma unroll
    for (int kc = 0; kc < 4; ++kc){
        uint32_t ah[2][4];
        #pragma unroll
        for (int mi = 0; mi < 2; ++mi){
            int row = wm*32 + mi*16 + rw + ((tt&1)<<3);
            int ch  = 2*kc + (tt>>1);
            ldsm4(sb + swz(row, ch), ah[mi]);
        }
        uint32_t b0[4][2], b1[4][2];
        #pragma unroll
        for (int jp = 0; jp < 2; ++jp){
            int row = wn*32 + jp*16 + rw + ((tt>>1)<<3);
            int ch  = 2*kc + (tt&1);
            uint32_t t4[4];
            ldsm4(sb + VA_BYTES + swz(row, ch), t4);
            b0[2*jp][0]=t4[0]; b0[2*jp][1]=t4[1];
            b0[2*jp+1][0]=t4[2]; b0[2*jp+1][1]=t4[3];
            ldsm4(sb + VA_BYTES + VB_BYTES + swz(row, ch), t4);
            b1[2*jp][0]=t4[0]; b1[2*jp][1]=t4[1];
            b1[2*jp+1][0]=t4[2]; b1[2*jp+1][1]=t4[3];
        }
        #pragma unroll
        for (int mi = 0; mi < 2; ++mi)
            #pragma unroll
            for (int nj = 0; nj < 4; ++nj){
                mma16816(a0[mi][nj], ah[mi], b0[nj]);
                mma16816(a1[mi][nj], ah[mi], b1[nj]);
            }
    }
}

__device__ __forceinline__ void gemm_ml_2b(const __half* Ah,
        const __half* B0, const __half* B1, uint32_t su,
        float a0[2][4][4], float a1[2][4][4])
{
    const int tid = threadIdx.x;
    const int lane = tid & 31, w = tid >> 5, wm = w & 3, wn = w >> 2;
    load_stage_2b(su,          Ah, B0, B1, 0,  tid); CP_COMMIT();
    load_stage_2b(su + VSTAGE, Ah, B0, B1, BK, tid); CP_COMMIT();
    for (int i = 0; i < DD/BK; ++i){
        CP_WAIT1();
        __syncthreads();
        if (i + 2 < DD/BK)
            load_stage_2b(su + ((i+2)%3)*VSTAGE, Ah, B0, B1, (i+2)*BK, tid);
        CP_COMMIT();
        compute_stage_2b(su + (i%3)*VSTAGE, lane, wm, wn, a0, a1);
    }
}

// ---------------- fused Vr+Vi projection + GLU gate ----------------
__device__ __forceinline__ float gatef(float v){
    float sp = (v > 20.f) ? v : log1pf(expf(v));
    return tanhf(sp);
}
__global__ __launch_bounds__(THREADS, 2) void proj_v(
    const float* __restrict__ bvr, const float* __restrict__ bvi)
{
    extern __shared__ char smem[];
    uint32_t su = smem_u32(smem);
    const int tid = threadIdx.x;
    const int lane = tid & 31, wrp = tid >> 5, wm = wrp & 3, wn = wrp >> 2;
    const int gn = blockIdx.x * 64;
    const int m0 = blockIdx.y * 128;

    const __half* Ah  = g_xh + (size_t)m0*DD;
    const __half* Bvr = g_Wh + (size_t)gn*DD;
    const __half* Bvi = g_Wh + (size_t)1*DD*DD + (size_t)gn*DD;

    float ar[2][4][4] = {}, ai[2][4][4] = {};
    gemm_ml_2b(Ah, Bvr, Bvi, su, ar, ai);

    #pragma unroll
    for (int mi = 0; mi < 2; ++mi)
        #pragma unroll
        for (int nj = 0; nj < 4; ++nj){
            int col = gn + wn*32 + nj*8 + 2*(lane&3);
            float br0 = bvr[col], br1 = bvr[col+1];
            float bi0 = bvi[col], bi1 = bvi[col+1];
            int row = m0 + wm*32 + mi*16 + (lane>>2);
            float v0 = (ar[mi][nj][0]+br0) * gatef(ai[mi][nj][0]+bi0);
            float v1 = (ar[mi][nj][1]+br1) * gatef(ai[mi][nj][1]+bi1);
            *(__half2*)(g_Vh + (size_t)row*DD + col) =
                __halves2half2(__float2half_rn(v0), __float2half_rn(v1));
            float v2 = (ar[mi][nj][2]+br0) * gatef(ai[mi][nj][2]+bi0);
            float v3 = (ar[mi][nj][3]+br1) * gatef(ai[mi][nj][3]+bi1);
            *(__half2*)(g_Vh + (size_t)(row+8)*DD + col) =
                __halves2half2(__float2half_rn(v2), __float2half_rn(v3));
        }
}

// ---------------- fused K+Q projection + norm partials ----------------
// grid (16, 256): gn = x*64, m0 = y*128
__global__ __launch_bounds__(THREADS, 2) void proj_kq(
    const float* __restrict__ bk, const float* __restrict__ bq)
{
    extern __shared__ char smem[];
    uint32_t su = smem_u32(smem);
    const int tid = threadIdx.x;
    const int lane = tid & 31, wrp = tid >> 5, wm = wrp & 3, wn = wrp >> 2;
    const int gn = blockIdx.x * 64;
    const int m0 = blockIdx.y * 128;

    const __half* Ah = g_xh + (size_t)m0*DD;
    const __half* Bk = g_Wh + (size_t)2*DD*DD + (size_t)gn*DD;
    const __half* Bq = g_Wh + (size_t)3*DD*DD + (size_t)gn*DD;

    float ak[2][4][4] = {}, aq[2][4][4] = {};
    gemm_ml_2b(Ah, Bk, Bq, su, ak, aq);

    float* sm = (float*)smem;
    const int b = m0 >> 12, n0 = m0 & 4095;
    #pragma unroll
    for (int p = 0; p < 2; ++p){
        __syncthreads();
        acc_to_sm_t64(sm, lane, wm, wn, p ? aq : ak);   // sm[d_local][m]
        __syncthreads();
        __half* dst = p ? g_Qth : g_Kth;
        const float* bias = p ? bq : bk;
        float* nsum = p ? g_nsQ : g_nsK;
        #pragma unroll
        for (int l = 0; l < 8; ++l){
            int idx = tid + l*THREADS;     // 2048 = 64 d x 32 q
            int d = idx >> 5, q = idx & 31;
            float bcol = bias[gn + d];
            float4 v = *(float4*)&sm[d*PADL + q*4];
            v.x += bcol; v.y += bcol; v.z += bcol; v.w += bcol;
            // norm partial: all 32 lanes of this warp share the same d
            float s = v.x*v.x + v.y*v.y + v.z*v.z + v.w*v.w;
            #pragma unroll
            for (int off = 16; off > 0; off >>= 1)
                s += __shfl_xor_sync(0xffffffffu, s, off);
            if ((tid & 31) == 0) atomicAdd(&nsum[b*DD + gn + d], s);
            size_t go = ((size_t)b*DD + gn + d)*NSEQ + n0 + q*4;
            __half2* ph = (__half2*)(dst + go);
            ph[0] = __halves2half2(__float2half_rn(v.x), __float2half_rn(v.y));
            ph[1] = __halves2half2(__float2half_rn(v.z), __float2half_rn(v.w));
        }
    }
}

// ---------------- feature attention (register epilogue) ----------------
__device__ __forceinline__ float smuf(float v){
    return 0.5f * (1.25f*v + 0.75f*v*erff(750000.f*v));
}
__global__ __launch_bounds__(THREADS, 2) void attn_mma(){
    extern __shared__ char smem[];
    uint32_t su = smem_u32(smem);
    const int tid = threadIdx.x;
    const int lane = tid & 31, wrp = tid >> 5, wm = wrp & 3, wn = wrp >> 2;
    const int b  = blockIdx.z;
    const int e0 = blockIdx.y * 128;
    const int d0 = blockIdx.x * 128;

    size_t qa = ((size_t)b*DD + e0)*NSEQ;
    size_t ka = ((size_t)b*DD + d0)*NSEQ;
    float acc[2][8][4] = {};
    gemm_ml(g_Qth + qa, NSEQ, g_Kth + ka, NSEQ, NSEQ/BK, su, acc);

    const float* sQ = g_sQ + b*DD;
    const float* sK = g_sK + b*DD;
    __half* Ap = g_Ath + (size_t)b*DD*DD;
    #pragma unroll
    for (int mi = 0; mi < 2; ++mi){
        int r0 = e0 + wm*32 + mi*16 + (lane>>2);
        float sq0 = sQ[r0], sq1 = sQ[r0+8];
        #pragma unroll
        for (int nj = 0; nj < 8; ++nj){
            int col = d0 + wn*64 + nj*8 + 2*(lane&3);
            float sk0 = sK[col], sk1 = sK[col+1];
            float* a = acc[mi][nj];
            *(__half2*)(Ap + (size_t)r0*DD + col) =
                __halves2half2(__float2half_rn(smuf(a[0]*sq0*sk0)),
                               __float2half_rn(smuf(a[1]*sq0*sk1)));
            *(__half2*)(Ap + (size_t)(r0+8)*DD + col) =
                __halves2half2(__float2half_rn(smuf(a[2]*sq1*sk0)),
                               __float2half_rn(smuf(a[3]*sq1*sk1)));
        }
    }
}

// ---------------- output (register epilogue) ----------------
__global__ __launch_bounds__(THREADS, 2) void out_mma(float* __restrict__ outp){
    extern __shared__ char smem[];
    uint32_t su = smem_u32(smem);
    const int tid = threadIdx.x;
    const int lane = tid & 31, wrp = tid >> 5, wm = wrp & 3, wn = wrp >> 2;
    const int m0 = blockIdx.y * 128;     // global token
    const int e0 = blockIdx.x * 128;
    const int b  = m0 >> 12;

    size_t va = (size_t)m0*DD;
    size_t aa = ((size_t)b*DD + e0)*DD;
    float acc[2][8][4] = {};
    gemm_ml(g_Vh + va, DD, g_Ath + aa, DD, DD/BK, su, acc);

    #pragma unroll
    for (int mi = 0; mi < 2; ++mi){
        int r0 = m0 + wm*32 + mi*16 + (lane>>2);
        #pragma unroll
        for (int nj = 0; nj < 8; ++nj){
            int col = e0 + wn*64 + nj*8 + 2*(lane&3);
            float* a = acc[mi][nj];
            *(float2*)(outp + (size_t)r0*DD + col)     = make_float2(a[0], a[1]);
            *(float2*)(outp + (size_t)(r0+8)*DD + col) = make_float2(a[2], a[3]);
        }
    }
}

// ---------------- launch ----------------
extern "C" void kernel_launch(void* const* d_in, const int* in_sizes, int n_in,
                              void* d_out, int out_size)
{
    const float* x   = (const float*)d_in[0];
    const float* Wvr = (const float*)d_in[1];
    const float* bvr = (const float*)d_in[2];
    const float* Wvi = (const float*)d_in[3];
    const float* bvi = (const float*)d_in[4];
    const float* Wk  = (const float*)d_in[5];
    const float* bk  = (const float*)d_in[6];
    const float* Wq  = (const float*)d_in[7];
    const float* bq  = (const float*)d_in[8];
    float* out = (float*)d_out;

    cudaFuncSetAttribute(proj_kq,  cudaFuncAttributeMaxDynamicSharedMemorySize, SMEM_BYTES);
    cudaFuncSetAttribute(proj_v,   cudaFuncAttributeMaxDynamicSharedMemorySize, SMEM_BYTES);
    cudaFuncSetAttribute(attn_mma, cudaFuncAttributeMaxDynamicSharedMemorySize, SMEM_BYTES);
    cudaFuncSetAttribute(out_mma,  cudaFuncAttributeMaxDynamicSharedMemorySize, SMEM_BYTES);

    conv_x<<<BB*NSEQ*DD/(256*4), 256>>>(x);
    conv_w<<<4*DD*DD/(256*4), 256>>>(Wvr, Wvi, Wk, Wq);
    zero_ns<<<BB*DD/256, 256>>>();
    proj_kq<<<dim3(16, 256), THREADS, SMEM_BYTES>>>(bk, bq);
    proj_v<<<dim3(16, 256), THREADS, SMEM_BYTES>>>(bvr, bvi);
    fin_ns<<<BB*DD/256, 256>>>();
    attn_mma<<<dim3(8, 8, BB), THREADS, SMEM_BYTES>>>();
    out_mma<<<dim3(8, 256), THREADS, SMEM_BYTES>>>(out);
}